// round 16
// baseline (speedup 1.0000x reference)
#include <cuda_runtime.h>
#include <cuda_fp16.h>
#include <math.h>
#include <stdint.h>

#define S_LEN   4096
#define DMODEL  1024
#define NHEADS  16
#define HDIM    64

// Scratch (allocation-free rule: device globals)
__device__ __half g_Xq[S_LEN * DMODEL];              // fp16 query input
__device__ __half g_Xk[S_LEN * DMODEL];              // fp16 key input
__device__ __half g_Xv[S_LEN * DMODEL];              // fp16 value input
__device__ __half g_WqT[DMODEL * DMODEL];            // W^T [n][k] fp16
__device__ __half g_WkT[DMODEL * DMODEL];
__device__ __half g_WvT[DMODEL * DMODEL];
__device__ __half g_WoT[DMODEL * DMODEL];
__device__ __half g_Qh[S_LEN * DMODEL];              // [s][d] fp16 projected Q
__device__ __half g_Kh[S_LEN * DMODEL];              // [s][d] fp16 projected K
__device__ __half g_VT[NHEADS * HDIM * S_LEN];       // [h][d][s] fp16 projected V
__device__ __half g_Ah[S_LEN * DMODEL];              // attention out fp16
__device__ float  g_ms[S_LEN];                       // mask additive (log2 dom)

// ---------------------------------------------------------------------------
// Helpers
// ---------------------------------------------------------------------------
__device__ __forceinline__ uint32_t pack_f16(float lo, float hi) {
    __half2 h = __floats2half2_rn(lo, hi);
    return *(uint32_t*)&h;
}

__device__ __forceinline__ void mma16(float* c,
    uint32_t a0, uint32_t a1, uint32_t a2, uint32_t a3,
    uint32_t b0, uint32_t b1)
{
    asm volatile(
        "mma.sync.aligned.m16n8k16.row.col.f32.f16.f16.f32 "
        "{%0,%1,%2,%3}, {%4,%5,%6,%7}, {%8,%9}, {%0,%1,%2,%3};"
        : "+f"(c[0]), "+f"(c[1]), "+f"(c[2]), "+f"(c[3])
        : "r"(a0), "r"(a1), "r"(a2), "r"(a3), "r"(b0), "r"(b1));
}

__device__ __forceinline__ void cp_async16(void* smem_ptr, const void* gptr) {
    uint32_t sa = (uint32_t)__cvta_generic_to_shared(smem_ptr);
    asm volatile("cp.async.cg.shared.global [%0], [%1], 16;" :: "r"(sa), "l"(gptr));
}

// ---------------------------------------------------------------------------
// Prepass 1: fp32 -> fp16 activations (rn).  grid (4096, 3), 256 thr.
// ---------------------------------------------------------------------------
__global__ __launch_bounds__(256) void cvt_act(
    const float* __restrict__ q, const float* __restrict__ k,
    const float* __restrict__ v,
    __half* __restrict__ qo, __half* __restrict__ ko, __half* __restrict__ vo)
{
    const float* src = (blockIdx.y == 0) ? q : (blockIdx.y == 1) ? k : v;
    __half* dst      = (blockIdx.y == 0) ? qo : (blockIdx.y == 1) ? ko : vo;
    int i = (blockIdx.x * 256 + threadIdx.x) * 4;
    float4 xv = *(const float4*)(src + i);
    uint2 o;
    o.x = pack_f16(xv.x, xv.y);
    o.y = pack_f16(xv.z, xv.w);
    *(uint2*)((uint32_t*)dst + i / 2) = o;
}

// Prepass 1b: mask -> additive float in log2 domain.  grid 16, 256 thr.
__global__ __launch_bounds__(256) void cvt_mask(
    const int* __restrict__ mask, float* __restrict__ msg)
{
    int i = blockIdx.x * 256 + threadIdx.x;
    msg[i] = (mask[i] == 0) ? -1.0e9f * 1.4426950408889634f : 0.f;
}

// ---------------------------------------------------------------------------
// Prepass 2: weight transpose+convert  W[k][n] fp32 -> WT[n][k] fp16.
// grid (32, 32, 4), 256 thr, 32x32 tiles via smem.
// ---------------------------------------------------------------------------
__global__ __launch_bounds__(256) void wtrans(
    const float* __restrict__ Wq, const float* __restrict__ Wk,
    const float* __restrict__ Wv, const float* __restrict__ Wo,
    __half* __restrict__ WqT, __half* __restrict__ WkT,
    __half* __restrict__ WvT, __half* __restrict__ WoT)
{
    __shared__ float t[32][33];
    const float* W = (blockIdx.z == 0) ? Wq : (blockIdx.z == 1) ? Wk
                   : (blockIdx.z == 2) ? Wv : Wo;
    __half* WT     = (blockIdx.z == 0) ? WqT : (blockIdx.z == 1) ? WkT
                   : (blockIdx.z == 2) ? WvT : WoT;
    int n0 = blockIdx.x * 32, k0 = blockIdx.y * 32;
    int tx = threadIdx.x & 31, ty = threadIdx.x >> 5;   // ty 0..7
#pragma unroll
    for (int i = 0; i < 4; i++) {
        int kl = ty * 4 + i;
        t[tx][kl] = W[(size_t)(k0 + kl) * DMODEL + n0 + tx];
    }
    __syncthreads();
#pragma unroll
    for (int i = 0; i < 4; i++) {
        int nl = ty * 4 + i;
        WT[(size_t)(n0 + nl) * DMODEL + k0 + tx] = __float2half_rn(t[nl][tx]);
    }
}

// ---------------------------------------------------------------------------
// FP16 GEMM: C[M,N] = A[M,K] @ W[K,N] + bias, with A fp16 [m][k] and
// WT fp16 [n][k] (both k-contiguous). cp.async 3-stage, BK=32, one barrier
// per iteration. BM=BN=128, 256 thr, 8 warps 2x4, warp tile 64m x 32n.
// mode: 0 = fp16 natural out, 2 = fp16 transposed [d][s] out, 3 = fp32 out.
// ---------------------------------------------------------------------------
#define HBK  32
#define HSA  20
#define STG_U (128 * HSA)              // u32 per operand per stage (2560)
#define SMEM_GEMM (3 * 2 * STG_U * 4)  // 61440 bytes

__device__ __forceinline__ void gemm_body(
    const __half* __restrict__ A, const __half* __restrict__ WT,
    const float* __restrict__ bias,
    float* __restrict__ Cf, __half* __restrict__ Ch,
    int N, int K, int bx, int by, int mode)
{
    extern __shared__ uint32_t smu[];

    const int tid = threadIdx.x;
    const int lane = tid & 31;
    const int w = tid >> 5;
    const int wm = (w >> 2) * 64;
    const int wn = (w & 3) * 32;
    const int gid = lane >> 2;
    const int tig = lane & 3;

    const int KU = K / 2;  // u32 per row
    const uint32_t* Agu = (const uint32_t*)(A) + (size_t)by * 128 * KU;
    const uint32_t* Bgu = (const uint32_t*)(WT) + (size_t)bx * 128 * KU;

    const int c0 = tid,        r0_ = c0 >> 2, kc0 = (c0 & 3) * 4;
    const int c1 = tid + 256,  r1_ = c1 >> 2, kc1 = (c1 & 3) * 4;

    float acc[4][4][4];
#pragma unroll
    for (int mt = 0; mt < 4; mt++)
#pragma unroll
        for (int nt = 0; nt < 4; nt++)
#pragma unroll
            for (int e = 0; e < 4; e++) acc[mt][nt][e] = 0.f;

#define G_ISSUE(k0u, sA, sB) do { \
        cp_async16(&(sA)[r0_ * HSA + kc0], Agu + (size_t)r0_ * KU + (k0u) + kc0); \
        cp_async16(&(sA)[r1_ * HSA + kc1], Agu + (size_t)r1_ * KU + (k0u) + kc1); \
        cp_async16(&(sB)[r0_ * HSA + kc0], Bgu + (size_t)r0_ * KU + (k0u) + kc0); \
        cp_async16(&(sB)[r1_ * HSA + kc1], Bgu + (size_t)r1_ * KU + (k0u) + kc1); \
        asm volatile("cp.async.commit_group;"); \
    } while (0)

    const int NIT = K / HBK;
    G_ISSUE(0,  smu + 0 * 2 * STG_U, smu + 0 * 2 * STG_U + STG_U);
    G_ISSUE(16, smu + 1 * 2 * STG_U, smu + 1 * 2 * STG_U + STG_U);

    for (int it = 0; it < NIT; it++) {
        if (it + 1 < NIT) asm volatile("cp.async.wait_group 1;");
        else              asm volatile("cp.async.wait_group 0;");
        __syncthreads();

        if (it + 2 < NIT) {
            uint32_t* sA = smu + ((it + 2) % 3) * 2 * STG_U;
            G_ISSUE((it + 2) * 16, sA, sA + STG_U);
        }

        uint32_t* As = smu + (it % 3) * 2 * STG_U;
        uint32_t* Bs = As + STG_U;

#pragma unroll
        for (int ks2 = 0; ks2 < 2; ks2++) {
            int col = ks2 * 8;
            uint32_t b[4][2];
#pragma unroll
            for (int nt = 0; nt < 4; nt++) {
                b[nt][0] = Bs[(wn + nt * 8 + gid) * HSA + col + tig];
                b[nt][1] = Bs[(wn + nt * 8 + gid) * HSA + col + tig + 4];
            }
#pragma unroll
            for (int mt = 0; mt < 4; mt++) {
                int r = wm + mt * 16 + gid;
                uint32_t a0 = As[r * HSA + col + tig];
                uint32_t a1 = As[(r + 8) * HSA + col + tig];
                uint32_t a2 = As[r * HSA + col + tig + 4];
                uint32_t a3 = As[(r + 8) * HSA + col + tig + 4];
#pragma unroll
                for (int nt = 0; nt < 4; nt++)
                    mma16(acc[mt][nt], a0, a1, a2, a3, b[nt][0], b[nt][1]);
            }
        }
        __syncthreads();
    }

    // epilogue
#pragma unroll
    for (int nt = 0; nt < 4; nt++) {
        int col = bx * 128 + wn + nt * 8 + 2 * tig;
        float b0 = bias[col], b1 = bias[col + 1];
#pragma unroll
        for (int mt = 0; mt < 4; mt++) {
            int row = by * 128 + wm + mt * 16 + gid;
            float c0v = acc[mt][nt][0] + b0;
            float c1v = acc[mt][nt][1] + b1;
            float c2v = acc[mt][nt][2] + b0;
            float c3v = acc[mt][nt][3] + b1;
            if (mode == 3) {
                float2 o;
                o.x = c0v; o.y = c1v;
                *(float2*)(&Cf[(size_t)row * N + col]) = o;
                o.x = c2v; o.y = c3v;
                *(float2*)(&Cf[(size_t)(row + 8) * N + col]) = o;
            } else if (mode == 2) {
                Ch[(size_t)col * S_LEN + row]           = __float2half_rn(c0v);
                Ch[(size_t)(col + 1) * S_LEN + row]     = __float2half_rn(c1v);
                Ch[(size_t)col * S_LEN + row + 8]       = __float2half_rn(c2v);
                Ch[(size_t)(col + 1) * S_LEN + row + 8] = __float2half_rn(c3v);
            } else {
                uint32_t* Cp = (uint32_t*)Ch;
                Cp[(size_t)row * (N / 2) + (col >> 1)]       = pack_f16(c0v, c1v);
                Cp[(size_t)(row + 8) * (N / 2) + (col >> 1)] = pack_f16(c2v, c3v);
            }
        }
    }
#undef G_ISSUE
}

// Fused Q/K/V projection: blockIdx.z selects which projection.
__global__ __launch_bounds__(256) void gemm_qkv(
    const __half* __restrict__ xq, const __half* __restrict__ xk,
    const __half* __restrict__ xv,
    const __half* __restrict__ WqT, const float* __restrict__ bq,
    const __half* __restrict__ WkT, const float* __restrict__ bk,
    const __half* __restrict__ WvT, const float* __restrict__ bv,
    __half* __restrict__ Qo, __half* __restrict__ Ko,
    __half* __restrict__ Vo)
{
    if (blockIdx.z == 0)
        gemm_body(xq, WqT, bq, nullptr, Qo, DMODEL, DMODEL, blockIdx.x, blockIdx.y, 0);
    else if (blockIdx.z == 1)
        gemm_body(xk, WkT, bk, nullptr, Ko, DMODEL, DMODEL, blockIdx.x, blockIdx.y, 0);
    else
        gemm_body(xv, WvT, bv, nullptr, Vo, DMODEL, DMODEL, blockIdx.x, blockIdx.y, 2);
}

__global__ __launch_bounds__(256) void gemm_out(
    const __half* __restrict__ A, const __half* __restrict__ WT,
    const float* __restrict__ bias, float* __restrict__ C)
{
    gemm_body(A, WT, bias, C, nullptr, DMODEL, DMODEL, blockIdx.x, blockIdx.y, 3);
}

// ---------------------------------------------------------------------------
// fp16 flash attention v5: triple-buffered K/V/mask stages (prefetch dist 2),
// ONE __syncthreads per key tile, register-resident P, conditional rescale.
// 256 threads, 8 warps, CTA = 128 q-rows; warp owns 16 rows x all 64 cols.
// Stage layout (u32): [K 64*36][V 64*36][ms 64 floats] = 4672 u32.
// ---------------------------------------------------------------------------
#define US 36
#define STG_ATT 4672                       // u32 per attention stage
#define SMEM_ATT ((128 * US + 3 * STG_ATT) * 4)   // 74496 bytes

__global__ __launch_bounds__(256, 2) void attn_f16(
    const __half* __restrict__ Qh, const __half* __restrict__ Kh,
    const __half* __restrict__ VTh, const float* __restrict__ msg,
    __half* __restrict__ Oh)
{
    extern __shared__ uint32_t smu[];
    uint32_t* Qs = smu;                    // 128*36 u32 (Q staging)
    uint32_t* St = smu + 128 * US;         // 3 stages

    const int h   = blockIdx.x;
    const int qb  = blockIdx.y;
    const int tid = threadIdx.x;
    const int lane = tid & 31;
    const int w = tid >> 5;
    const int wbase = w * 16;
    const int gid = lane >> 2;
    const int tig = lane & 3;
    const int r0 = wbase + gid;            // owned rows: r0, r0+8

    const float LOG2E = 1.4426950408889634f;
    const float SCALE = 0.125f * LOG2E;

    const uint32_t* Qg = (const uint32_t*)Qh;
    const uint32_t* Kg = (const uint32_t*)Kh;
    const uint32_t* Vg = (const uint32_t*)VTh;

    const int lrow0 = tid >> 3,  lq0 = (tid & 7) * 4;
    const int lrow1 = (256 + tid) >> 3, lq1 = ((256 + tid) & 7) * 4;

#define ISSUE_TILE(kb, stg) do { \
        uint32_t* Kbuf = (stg); \
        uint32_t* Vbuf = (stg) + 2304; \
        cp_async16(&Kbuf[lrow0 * US + lq0], \
            Kg + (size_t)((kb) * 64 + lrow0) * (DMODEL / 2) + h * 32 + lq0); \
        cp_async16(&Kbuf[lrow1 * US + lq1], \
            Kg + (size_t)((kb) * 64 + lrow1) * (DMODEL / 2) + h * 32 + lq1); \
        cp_async16(&Vbuf[lrow0 * US + lq0], \
            Vg + (size_t)(h * HDIM + lrow0) * (S_LEN / 2) + (kb) * 32 + lq0); \
        cp_async16(&Vbuf[lrow1 * US + lq1], \
            Vg + (size_t)(h * HDIM + lrow1) * (S_LEN / 2) + (kb) * 32 + lq1); \
        if (tid < 16) \
            cp_async16((float*)((stg) + 4608) + tid * 4, msg + (kb) * 64 + tid * 4); \
        asm volatile("cp.async.commit_group;"); \
    } while (0)

    // ---- prologue: start tiles 0,1; stage Q; hoist Q fragments ----
    ISSUE_TILE(0, St);
    ISSUE_TILE(1, St + STG_ATT);

#pragma unroll
    for (int it = 0; it < 4; it++) {
        int lin = it * 256 + tid;
        int row = lin >> 3, q4 = (lin & 7) * 4;
        *(uint4*)&Qs[row * US + q4] =
            *(const uint4*)(Qg + (size_t)(qb * 128 + row) * (DMODEL / 2) + h * 32 + q4);
    }
    __syncthreads();

    uint32_t q[4][4];
#pragma unroll
    for (int c = 0; c < 4; c++) {
        q[c][0] = Qs[r0 * US + c * 8 + tig];
        q[c][1] = Qs[(r0 + 8) * US + c * 8 + tig];
        q[c][2] = Qs[r0 * US + c * 8 + tig + 4];
        q[c][3] = Qs[(r0 + 8) * US + c * 8 + tig + 4];
    }

    float o[8][4];
    float m0 = -1e30f, m1 = -1e30f, l0 = 0.f, l1 = 0.f;
#pragma unroll
    for (int nt = 0; nt < 8; nt++)
#pragma unroll
        for (int e = 0; e < 4; e++) o[nt][e] = 0.f;

    const int NT = S_LEN / 64;
    for (int kb = 0; kb < NT; kb++) {
        if (kb + 1 < NT) asm volatile("cp.async.wait_group 1;");
        else             asm volatile("cp.async.wait_group 0;");
        __syncthreads();   // tile kb visible; all warps finished tile kb-1

        if (kb + 2 < NT)
            ISSUE_TILE(kb + 2, St + ((kb + 2) % 3) * STG_ATT);

        uint32_t* stg = St + (kb % 3) * STG_ATT;
        uint32_t* Kb  = stg;
        uint32_t* Vb  = stg + 2304;
        float*    msf = (float*)(stg + 4608);

        // ---- S = Q @ K^T : 16 rows x 64 cols per warp ----
        float s[8][4];
#pragma unroll
        for (int nt = 0; nt < 8; nt++)
#pragma unroll
            for (int e = 0; e < 4; e++) s[nt][e] = 0.f;

#pragma unroll
        for (int c = 0; c < 4; c++) {
#pragma unroll
            for (int nt = 0; nt < 8; nt++) {
                int kr = nt * 8 + gid;
                uint32_t b0 = Kb[kr * US + c * 8 + tig];
                uint32_t b1 = Kb[kr * US + c * 8 + tig + 4];
                mma16(s[nt], q[c][0], q[c][1], q[c][2], q[c][3], b0, b1);
            }
        }

        // ---- warp-local online softmax (log2 domain) ----
        float mx0 = -1e30f, mx1 = -1e30f;
#pragma unroll
        for (int nt = 0; nt < 8; nt++) {
            int col = nt * 8 + 2 * tig;
            float mk0 = msf[col], mk1 = msf[col + 1];
            s[nt][0] = s[nt][0] * SCALE + mk0;
            s[nt][1] = s[nt][1] * SCALE + mk1;
            s[nt][2] = s[nt][2] * SCALE + mk0;
            s[nt][3] = s[nt][3] * SCALE + mk1;
            mx0 = fmaxf(mx0, fmaxf(s[nt][0], s[nt][1]));
            mx1 = fmaxf(mx1, fmaxf(s[nt][2], s[nt][3]));
        }
        mx0 = fmaxf(mx0, __shfl_xor_sync(0xffffffffu, mx0, 1));
        mx0 = fmaxf(mx0, __shfl_xor_sync(0xffffffffu, mx0, 2));
        mx1 = fmaxf(mx1, __shfl_xor_sync(0xffffffffu, mx1, 1));
        mx1 = fmaxf(mx1, __shfl_xor_sync(0xffffffffu, mx1, 2));

        bool need = (mx0 > m0) || (mx1 > m1);
        float nm0 = fmaxf(m0, mx0);
        float nm1 = fmaxf(m1, mx1);
        float f0 = exp2f(m0 - nm0);
        float f1 = exp2f(m1 - nm1);
        m0 = nm0; m1 = nm1;

        // p = exp2(s - m), packed directly into PV A-operand fragments
        uint32_t a[4][4];
        float sum0 = 0.f, sum1 = 0.f;
#pragma unroll
        for (int nt = 0; nt < 8; nt++) {
            float p0 = exp2f(s[nt][0] - nm0);
            float p1 = exp2f(s[nt][1] - nm0);
            float p2 = exp2f(s[nt][2] - nm1);
            float p3 = exp2f(s[nt][3] - nm1);
            sum0 += p0 + p1; sum1 += p2 + p3;
            int c = nt >> 1;
            if ((nt & 1) == 0) {
                a[c][0] = pack_f16(p0, p1);
                a[c][1] = pack_f16(p2, p3);
            } else {
                a[c][2] = pack_f16(p0, p1);
                a[c][3] = pack_f16(p2, p3);
            }
        }
        sum0 += __shfl_xor_sync(0xffffffffu, sum0, 1);
        sum0 += __shfl_xor_sync(0xffffffffu, sum0, 2);
        sum1 += __shfl_xor_sync(0xffffffffu, sum1, 1);
        sum1 += __shfl_xor_sync(0xffffffffu, sum1, 2);
        l0 = l0 * f0 + sum0;
        l1 = l1 * f1 + sum1;

        if (__any_sync(0xffffffffu, need)) {
#pragma unroll
            for (int nt = 0; nt < 8; nt++) {
                o[nt][0] *= f0; o[nt][1] *= f0;
                o[nt][2] *= f1; o[nt][3] *= f1;
            }
        }

        // ---- O += P @ V (P register-resident) ----
#pragma unroll
        for (int c = 0; c < 4; c++) {
#pragma unroll
            for (int nt = 0; nt < 8; nt++) {
                int dc = nt * 8 + gid;
                uint32_t b0 = Vb[dc * US + c * 8 + tig];
                uint32_t b1 = Vb[dc * US + c * 8 + tig + 4];
                mma16(o[nt], a[c][0], a[c][1], a[c][2], a[c][3], b0, b1);
            }
        }
        // no bottom barrier: stage reuse protected by next iteration's top
        // barrier (stage (kb+3)%3 == kb%3 is only refilled at iter kb+1,
        // after every warp has passed the barrier that follows tile kb).
    }

    // ---- normalize + write fp16 ----
    float inv0 = 1.f / fmaxf(l0, 1e-20f);
    float inv1 = 1.f / fmaxf(l1, 1e-20f);
    uint32_t* Og = (uint32_t*)Oh;
#pragma unroll
    for (int nt = 0; nt < 8; nt++) {
        int cp = h * 32 + nt * 4 + tig;   // u32 (half-pair) column index
        Og[(size_t)(qb * 128 + r0) * (DMODEL / 2) + cp] =
            pack_f16(o[nt][0] * inv0, o[nt][1] * inv0);
        Og[(size_t)(qb * 128 + r0 + 8) * (DMODEL / 2) + cp] =
            pack_f16(o[nt][2] * inv1, o[nt][3] * inv1);
    }
#undef ISSUE_TILE
}

// ---------------------------------------------------------------------------
extern "C" void kernel_launch(void* const* d_in, const int* in_sizes, int n_in,
                              void* d_out, int out_size)
{
    (void)in_sizes; (void)n_in; (void)out_size;
    const float* query = (const float*)d_in[0];
    const float* key   = (const float*)d_in[1];
    const float* value = (const float*)d_in[2];
    const int*   amask = (const int*)  d_in[3];
    const float* Wq = (const float*)d_in[4];
    const float* bq = (const float*)d_in[5];
    const float* Wk = (const float*)d_in[6];
    const float* bk = (const float*)d_in[7];
    const float* Wv = (const float*)d_in[8];
    const float* bv = (const float*)d_in[9];
    const float* Wo = (const float*)d_in[10];
    const float* bo = (const float*)d_in[11];
    float* out = (float*)d_out;

    __half *Xq, *Xk, *Xv, *WqT, *WkT, *WvT, *WoT, *Qhp, *Khp, *VTp, *Ahp;
    float *msp;
    cudaGetSymbolAddress((void**)&Xq,  g_Xq);
    cudaGetSymbolAddress((void**)&Xk,  g_Xk);
    cudaGetSymbolAddress((void**)&Xv,  g_Xv);
    cudaGetSymbolAddress((void**)&WqT, g_WqT);
    cudaGetSymbolAddress((void**)&WkT, g_WkT);
    cudaGetSymbolAddress((void**)&WvT, g_WvT);
    cudaGetSymbolAddress((void**)&WoT, g_WoT);
    cudaGetSymbolAddress((void**)&Qhp, g_Qh);
    cudaGetSymbolAddress((void**)&Khp, g_Kh);
    cudaGetSymbolAddress((void**)&VTp, g_VT);
    cudaGetSymbolAddress((void**)&Ahp, g_Ah);
    cudaGetSymbolAddress((void**)&msp, g_ms);

    // Prepasses: activations->fp16, mask->float, weights->fp16 transposed
    cvt_act<<<dim3(S_LEN * DMODEL / 1024, 3), 256>>>(query, key, value, Xq, Xk, Xv);
    cvt_mask<<<S_LEN / 256, 256>>>(amask, msp);
    wtrans<<<dim3(DMODEL / 32, DMODEL / 32, 4), 256>>>(
        Wq, Wk, Wv, Wo, WqT, WkT, WvT, WoT);

    // Fused Q/K/V projections (pure fp16 cp.async GEMM; V pre-transposed)
    cudaFuncSetAttribute(gemm_qkv,
                         cudaFuncAttributeMaxDynamicSharedMemorySize, SMEM_GEMM);
    gemm_qkv<<<dim3(DMODEL / 128, S_LEN / 128, 3), 256, SMEM_GEMM>>>(
        Xq, Xk, Xv, WqT, bq, WkT, bk, WvT, bv, Qhp, Khp, VTp);

    cudaFuncSetAttribute(attn_f16,
                         cudaFuncAttributeMaxDynamicSharedMemorySize, SMEM_ATT);
    attn_f16<<<dim3(NHEADS, S_LEN / 128), 256, SMEM_ATT>>>(Qhp, Khp, VTp, msp, Ahp);

    cudaFuncSetAttribute(gemm_out,
                         cudaFuncAttributeMaxDynamicSharedMemorySize, SMEM_GEMM);
    gemm_out<<<dim3(DMODEL / 128, S_LEN / 128), 256, SMEM_GEMM>>>(Ahp, WoT, bo, out);
}

// round 17
// speedup vs baseline: 1.0455x; 1.0455x over previous
#include <cuda_runtime.h>
#include <cuda_fp16.h>
#include <math.h>
#include <stdint.h>

#define S_LEN   4096
#define DMODEL  1024
#define NHEADS  16
#define HDIM    64

// Scratch (allocation-free rule: device globals)
__device__ __half g_Xq[S_LEN * DMODEL];              // fp16 query input
__device__ __half g_Xk[S_LEN * DMODEL];              // fp16 key input
__device__ __half g_Xv[S_LEN * DMODEL];              // fp16 value input
__device__ __half g_WqT[DMODEL * DMODEL];            // W^T [n][k] fp16
__device__ __half g_WkT[DMODEL * DMODEL];
__device__ __half g_WvT[DMODEL * DMODEL];
__device__ __half g_WoT[DMODEL * DMODEL];
__device__ __half g_Qh[S_LEN * DMODEL];              // [s][d] fp16 projected Q
__device__ __half g_Kh[S_LEN * DMODEL];              // [s][d] fp16 projected K
__device__ __half g_VT[NHEADS * HDIM * S_LEN];       // [h][d][s] fp16 projected V
__device__ __half g_Ah[S_LEN * DMODEL];              // attention out fp16
__device__ float  g_ms[S_LEN];                       // mask additive (log2 dom)

// ---------------------------------------------------------------------------
// Helpers
// ---------------------------------------------------------------------------
__device__ __forceinline__ uint32_t pack_f16(float lo, float hi) {
    __half2 h = __floats2half2_rn(lo, hi);
    return *(uint32_t*)&h;
}

__device__ __forceinline__ void mma16(float* c,
    uint32_t a0, uint32_t a1, uint32_t a2, uint32_t a3,
    uint32_t b0, uint32_t b1)
{
    asm volatile(
        "mma.sync.aligned.m16n8k16.row.col.f32.f16.f16.f32 "
        "{%0,%1,%2,%3}, {%4,%5,%6,%7}, {%8,%9}, {%0,%1,%2,%3};"
        : "+f"(c[0]), "+f"(c[1]), "+f"(c[2]), "+f"(c[3])
        : "r"(a0), "r"(a1), "r"(a2), "r"(a3), "r"(b0), "r"(b1));
}

__device__ __forceinline__ void cp_async16(void* smem_ptr, const void* gptr) {
    uint32_t sa = (uint32_t)__cvta_generic_to_shared(smem_ptr);
    asm volatile("cp.async.cg.shared.global [%0], [%1], 16;" :: "r"(sa), "l"(gptr));
}

__device__ __forceinline__ void ldsm_x4(
    uint32_t& r0, uint32_t& r1, uint32_t& r2, uint32_t& r3, uint32_t addr)
{
    asm volatile(
        "ldmatrix.sync.aligned.m8n8.x4.shared.b16 {%0,%1,%2,%3}, [%4];"
        : "=r"(r0), "=r"(r1), "=r"(r2), "=r"(r3) : "r"(addr));
}

// ---------------------------------------------------------------------------
// Prepass 1: fp32 -> fp16 activations (rn).  grid (4096, 3), 256 thr.
// ---------------------------------------------------------------------------
__global__ __launch_bounds__(256) void cvt_act(
    const float* __restrict__ q, const float* __restrict__ k,
    const float* __restrict__ v,
    __half* __restrict__ qo, __half* __restrict__ ko, __half* __restrict__ vo)
{
    const float* src = (blockIdx.y == 0) ? q : (blockIdx.y == 1) ? k : v;
    __half* dst      = (blockIdx.y == 0) ? qo : (blockIdx.y == 1) ? ko : vo;
    int i = (blockIdx.x * 256 + threadIdx.x) * 4;
    float4 xv = *(const float4*)(src + i);
    uint2 o;
    o.x = pack_f16(xv.x, xv.y);
    o.y = pack_f16(xv.z, xv.w);
    *(uint2*)((uint32_t*)dst + i / 2) = o;
}

// Prepass 1b: mask -> additive float in log2 domain.  grid 16, 256 thr.
__global__ __launch_bounds__(256) void cvt_mask(
    const int* __restrict__ mask, float* __restrict__ msg)
{
    int i = blockIdx.x * 256 + threadIdx.x;
    msg[i] = (mask[i] == 0) ? -1.0e9f * 1.4426950408889634f : 0.f;
}

// ---------------------------------------------------------------------------
// Prepass 2: weight transpose+convert  W[k][n] fp32 -> WT[n][k] fp16.
// ---------------------------------------------------------------------------
__global__ __launch_bounds__(256) void wtrans(
    const float* __restrict__ Wq, const float* __restrict__ Wk,
    const float* __restrict__ Wv, const float* __restrict__ Wo,
    __half* __restrict__ WqT, __half* __restrict__ WkT,
    __half* __restrict__ WvT, __half* __restrict__ WoT)
{
    __shared__ float t[32][33];
    const float* W = (blockIdx.z == 0) ? Wq : (blockIdx.z == 1) ? Wk
                   : (blockIdx.z == 2) ? Wv : Wo;
    __half* WT     = (blockIdx.z == 0) ? WqT : (blockIdx.z == 1) ? WkT
                   : (blockIdx.z == 2) ? WvT : WoT;
    int n0 = blockIdx.x * 32, k0 = blockIdx.y * 32;
    int tx = threadIdx.x & 31, ty = threadIdx.x >> 5;   // ty 0..7
#pragma unroll
    for (int i = 0; i < 4; i++) {
        int kl = ty * 4 + i;
        t[tx][kl] = W[(size_t)(k0 + kl) * DMODEL + n0 + tx];
    }
    __syncthreads();
#pragma unroll
    for (int i = 0; i < 4; i++) {
        int nl = ty * 4 + i;
        WT[(size_t)(n0 + nl) * DMODEL + k0 + tx] = __float2half_rn(t[nl][tx]);
    }
}

// ---------------------------------------------------------------------------
// FP16 GEMM (proven R12): cp.async 3-stage, BK=32, one barrier per iteration.
// BM=BN=128, 256 thr, 8 warps 2x4, warp tile 64m x 32n.
// mode: 0 = fp16 natural out, 2 = fp16 transposed [d][s] out, 3 = fp32 out.
// ---------------------------------------------------------------------------
#define HBK  32
#define HSA  20
#define STG_U (128 * HSA)              // u32 per operand per stage (2560)
#define SMEM_GEMM (3 * 2 * STG_U * 4)  // 61440 bytes

__device__ __forceinline__ void gemm_body(
    const __half* __restrict__ A, const __half* __restrict__ WT,
    const float* __restrict__ bias,
    float* __restrict__ Cf, __half* __restrict__ Ch,
    int N, int K, int bx, int by, int mode)
{
    extern __shared__ uint32_t smu[];

    const int tid = threadIdx.x;
    const int lane = tid & 31;
    const int w = tid >> 5;
    const int wm = (w >> 2) * 64;
    const int wn = (w & 3) * 32;
    const int gid = lane >> 2;
    const int tig = lane & 3;

    const int KU = K / 2;  // u32 per row
    const uint32_t* Agu = (const uint32_t*)(A) + (size_t)by * 128 * KU;
    const uint32_t* Bgu = (const uint32_t*)(WT) + (size_t)bx * 128 * KU;

    const int c0 = tid,        r0_ = c0 >> 2, kc0 = (c0 & 3) * 4;
    const int c1 = tid + 256,  r1_ = c1 >> 2, kc1 = (c1 & 3) * 4;

    float acc[4][4][4];
#pragma unroll
    for (int mt = 0; mt < 4; mt++)
#pragma unroll
        for (int nt = 0; nt < 4; nt++)
#pragma unroll
            for (int e = 0; e < 4; e++) acc[mt][nt][e] = 0.f;

#define G_ISSUE(k0u, sA, sB) do { \
        cp_async16(&(sA)[r0_ * HSA + kc0], Agu + (size_t)r0_ * KU + (k0u) + kc0); \
        cp_async16(&(sA)[r1_ * HSA + kc1], Agu + (size_t)r1_ * KU + (k0u) + kc1); \
        cp_async16(&(sB)[r0_ * HSA + kc0], Bgu + (size_t)r0_ * KU + (k0u) + kc0); \
        cp_async16(&(sB)[r1_ * HSA + kc1], Bgu + (size_t)r1_ * KU + (k0u) + kc1); \
        asm volatile("cp.async.commit_group;"); \
    } while (0)

    const int NIT = K / HBK;
    G_ISSUE(0,  smu + 0 * 2 * STG_U, smu + 0 * 2 * STG_U + STG_U);
    G_ISSUE(16, smu + 1 * 2 * STG_U, smu + 1 * 2 * STG_U + STG_U);

    for (int it = 0; it < NIT; it++) {
        if (it + 1 < NIT) asm volatile("cp.async.wait_group 1;");
        else              asm volatile("cp.async.wait_group 0;");
        __syncthreads();

        if (it + 2 < NIT) {
            uint32_t* sA = smu + ((it + 2) % 3) * 2 * STG_U;
            G_ISSUE((it + 2) * 16, sA, sA + STG_U);
        }

        uint32_t* As = smu + (it % 3) * 2 * STG_U;
        uint32_t* Bs = As + STG_U;

#pragma unroll
        for (int ks2 = 0; ks2 < 2; ks2++) {
            int col = ks2 * 8;
            uint32_t b[4][2];
#pragma unroll
            for (int nt = 0; nt < 4; nt++) {
                b[nt][0] = Bs[(wn + nt * 8 + gid) * HSA + col + tig];
                b[nt][1] = Bs[(wn + nt * 8 + gid) * HSA + col + tig + 4];
            }
#pragma unroll
            for (int mt = 0; mt < 4; mt++) {
                int r = wm + mt * 16 + gid;
                uint32_t a0 = As[r * HSA + col + tig];
                uint32_t a1 = As[(r + 8) * HSA + col + tig];
                uint32_t a2 = As[r * HSA + col + tig + 4];
                uint32_t a3 = As[(r + 8) * HSA + col + tig + 4];
#pragma unroll
                for (int nt = 0; nt < 4; nt++)
                    mma16(acc[mt][nt], a0, a1, a2, a3, b[nt][0], b[nt][1]);
            }
        }
        __syncthreads();
    }

    // epilogue
#pragma unroll
    for (int nt = 0; nt < 4; nt++) {
        int col = bx * 128 + wn + nt * 8 + 2 * tig;
        float b0 = bias[col], b1 = bias[col + 1];
#pragma unroll
        for (int mt = 0; mt < 4; mt++) {
            int row = by * 128 + wm + mt * 16 + gid;
            float c0v = acc[mt][nt][0] + b0;
            float c1v = acc[mt][nt][1] + b1;
            float c2v = acc[mt][nt][2] + b0;
            float c3v = acc[mt][nt][3] + b1;
            if (mode == 3) {
                float2 o;
                o.x = c0v; o.y = c1v;
                *(float2*)(&Cf[(size_t)row * N + col]) = o;
                o.x = c2v; o.y = c3v;
                *(float2*)(&Cf[(size_t)(row + 8) * N + col]) = o;
            } else if (mode == 2) {
                Ch[(size_t)col * S_LEN + row]           = __float2half_rn(c0v);
                Ch[(size_t)(col + 1) * S_LEN + row]     = __float2half_rn(c1v);
                Ch[(size_t)col * S_LEN + row + 8]       = __float2half_rn(c2v);
                Ch[(size_t)(col + 1) * S_LEN + row + 8] = __float2half_rn(c3v);
            } else {
                uint32_t* Cp = (uint32_t*)Ch;
                Cp[(size_t)row * (N / 2) + (col >> 1)]       = pack_f16(c0v, c1v);
                Cp[(size_t)(row + 8) * (N / 2) + (col >> 1)] = pack_f16(c2v, c3v);
            }
        }
    }
#undef G_ISSUE
}

// Fused Q/K/V projection: blockIdx.z selects which projection.
__global__ __launch_bounds__(256) void gemm_qkv(
    const __half* __restrict__ xq, const __half* __restrict__ xk,
    const __half* __restrict__ xv,
    const __half* __restrict__ WqT, const float* __restrict__ bq,
    const __half* __restrict__ WkT, const float* __restrict__ bk,
    const __half* __restrict__ WvT, const float* __restrict__ bv,
    __half* __restrict__ Qo, __half* __restrict__ Ko,
    __half* __restrict__ Vo)
{
    if (blockIdx.z == 0)
        gemm_body(xq, WqT, bq, nullptr, Qo, DMODEL, DMODEL, blockIdx.x, blockIdx.y, 0);
    else if (blockIdx.z == 1)
        gemm_body(xk, WkT, bk, nullptr, Ko, DMODEL, DMODEL, blockIdx.x, blockIdx.y, 0);
    else
        gemm_body(xv, WvT, bv, nullptr, Vo, DMODEL, DMODEL, blockIdx.x, blockIdx.y, 2);
}

__global__ __launch_bounds__(256) void gemm_out(
    const __half* __restrict__ A, const __half* __restrict__ WT,
    const float* __restrict__ bias, float* __restrict__ C)
{
    gemm_body(A, WT, bias, C, nullptr, DMODEL, DMODEL, blockIdx.x, blockIdx.y, 3);
}

// ---------------------------------------------------------------------------
// fp16 flash attention v6: LDSM fragment loads (1 ldmatrix.x4 = 4 LDS),
// triple-buffered K/V/mask stages, one barrier per tile, register-resident P.
// 256 threads, 8 warps, CTA = 128 q-rows; warp owns 16 rows x all 64 cols.
// Stage layout (u32): [K 64*36][V 64*36][ms 64 floats] = 4672 u32.
// LDSM conflict-free: rows at 144B stride -> 16i mod 128, all distinct.
// ---------------------------------------------------------------------------
#define US 36
#define STG_ATT 4672                       // u32 per attention stage
#define SMEM_ATT ((128 * US + 3 * STG_ATT) * 4)   // 74496 bytes

__global__ __launch_bounds__(256, 2) void attn_f16(
    const __half* __restrict__ Qh, const __half* __restrict__ Kh,
    const __half* __restrict__ VTh, const float* __restrict__ msg,
    __half* __restrict__ Oh)
{
    extern __shared__ uint32_t smu[];
    uint32_t* Qs = smu;                    // 128*36 u32 (Q staging)
    uint32_t* St = smu + 128 * US;         // 3 stages

    const int h   = blockIdx.x;
    const int qb  = blockIdx.y;
    const int tid = threadIdx.x;
    const int lane = tid & 31;
    const int w = tid >> 5;
    const int wbase = w * 16;
    const int gid = lane >> 2;
    const int tig = lane & 3;
    const int r0 = wbase + gid;            // owned rows: r0, r0+8

    const float LOG2E = 1.4426950408889634f;
    const float SCALE = 0.125f * LOG2E;

    const uint32_t* Qg = (const uint32_t*)Qh;
    const uint32_t* Kg = (const uint32_t*)Kh;
    const uint32_t* Vg = (const uint32_t*)VTh;

    const int lrow0 = tid >> 3,  lq0 = (tid & 7) * 4;
    const int lrow1 = (256 + tid) >> 3, lq1 = ((256 + tid) & 7) * 4;

    // ldmatrix per-lane address components:
    // lanes 0-7: rows +L, k-lo | 8-15: rows +L, k-hi
    // lanes 16-23: rows +8+L, k-lo | 24-31: rows +8+L, k-hi
    const int Ll  = lane & 7;
    const int grp = lane >> 3;
    const uint32_t offKV = (uint32_t)((((grp >> 1) * 8 + Ll) * US + (grp & 1) * 4) * 4);

    uint32_t stage_k[3], stage_v[3];
#pragma unroll
    for (int si = 0; si < 3; si++) {
        uint32_t b = (uint32_t)__cvta_generic_to_shared(St + si * STG_ATT);
        stage_k[si] = b + offKV;
        stage_v[si] = b + 2304 * 4 + offKV;
    }

#define ISSUE_TILE(kb, stg) do { \
        uint32_t* Kbuf = (stg); \
        uint32_t* Vbuf = (stg) + 2304; \
        cp_async16(&Kbuf[lrow0 * US + lq0], \
            Kg + (size_t)((kb) * 64 + lrow0) * (DMODEL / 2) + h * 32 + lq0); \
        cp_async16(&Kbuf[lrow1 * US + lq1], \
            Kg + (size_t)((kb) * 64 + lrow1) * (DMODEL / 2) + h * 32 + lq1); \
        cp_async16(&Vbuf[lrow0 * US + lq0], \
            Vg + (size_t)(h * HDIM + lrow0) * (S_LEN / 2) + (kb) * 32 + lq0); \
        cp_async16(&Vbuf[lrow1 * US + lq1], \
            Vg + (size_t)(h * HDIM + lrow1) * (S_LEN / 2) + (kb) * 32 + lq1); \
        if (tid < 16) \
            cp_async16((float*)((stg) + 4608) + tid * 4, msg + (kb) * 64 + tid * 4); \
        asm volatile("cp.async.commit_group;"); \
    } while (0)

    // ---- prologue: start tiles 0,1; stage Q; hoist Q fragments ----
    ISSUE_TILE(0, St);
    ISSUE_TILE(1, St + STG_ATT);

#pragma unroll
    for (int it = 0; it < 4; it++) {
        int lin = it * 256 + tid;
        int row = lin >> 3, q4 = (lin & 7) * 4;
        *(uint4*)&Qs[row * US + q4] =
            *(const uint4*)(Qg + (size_t)(qb * 128 + row) * (DMODEL / 2) + h * 32 + q4);
    }
    __syncthreads();

    uint32_t q[4][4];
#pragma unroll
    for (int c = 0; c < 4; c++) {
        q[c][0] = Qs[r0 * US + c * 8 + tig];
        q[c][1] = Qs[(r0 + 8) * US + c * 8 + tig];
        q[c][2] = Qs[r0 * US + c * 8 + tig + 4];
        q[c][3] = Qs[(r0 + 8) * US + c * 8 + tig + 4];
    }

    float o[8][4];
    float m0 = -1e30f, m1 = -1e30f, l0 = 0.f, l1 = 0.f;
#pragma unroll
    for (int nt = 0; nt < 8; nt++)
#pragma unroll
        for (int e = 0; e < 4; e++) o[nt][e] = 0.f;

    const int NT = S_LEN / 64;
    for (int kb = 0; kb < NT; kb++) {
        if (kb + 1 < NT) asm volatile("cp.async.wait_group 1;");
        else             asm volatile("cp.async.wait_group 0;");
        __syncthreads();   // tile kb visible; all warps finished tile kb-1

        if (kb + 2 < NT)
            ISSUE_TILE(kb + 2, St + ((kb + 2) % 3) * STG_ATT);

        const int si = kb % 3;
        const uint32_t ka = stage_k[si];
        const uint32_t va = stage_v[si];
        float* msf = (float*)(St + si * STG_ATT + 4608);

        // ---- S = Q @ K^T : LDSM x4 loads fragments for 2 n-tiles at once ----
        float s[8][4];
#pragma unroll
        for (int nt = 0; nt < 8; nt++)
#pragma unroll
            for (int e = 0; e < 4; e++) s[nt][e] = 0.f;

#pragma unroll
        for (int c = 0; c < 4; c++) {
#pragma unroll
            for (int ntp = 0; ntp < 4; ntp++) {
                uint32_t b0, b1, b2, b3;
                ldsm_x4(b0, b1, b2, b3, ka + ntp * (16 * US * 4) + c * 32);
                mma16(s[2 * ntp],     q[c][0], q[c][1], q[c][2], q[c][3], b0, b1);
                mma16(s[2 * ntp + 1], q[c][0], q[c][1], q[c][2], q[c][3], b2, b3);
            }
        }

        // ---- warp-local online softmax (log2 domain) ----
        float mx0 = -1e30f, mx1 = -1e30f;
#pragma unroll
        for (int nt = 0; nt < 8; nt++) {
            int col = nt * 8 + 2 * tig;
            float mk0 = msf[col], mk1 = msf[col + 1];
            s[nt][0] = s[nt][0] * SCALE + mk0;
            s[nt][1] = s[nt][1] * SCALE + mk1;
            s[nt][2] = s[nt][2] * SCALE + mk0;
            s[nt][3] = s[nt][3] * SCALE + mk1;
            mx0 = fmaxf(mx0, fmaxf(s[nt][0], s[nt][1]));
            mx1 = fmaxf(mx1, fmaxf(s[nt][2], s[nt][3]));
        }
        mx0 = fmaxf(mx0, __shfl_xor_sync(0xffffffffu, mx0, 1));
        mx0 = fmaxf(mx0, __shfl_xor_sync(0xffffffffu, mx0, 2));
        mx1 = fmaxf(mx1, __shfl_xor_sync(0xffffffffu, mx1, 1));
        mx1 = fmaxf(mx1, __shfl_xor_sync(0xffffffffu, mx1, 2));

        bool need = (mx0 > m0) || (mx1 > m1);
        float nm0 = fmaxf(m0, mx0);
        float nm1 = fmaxf(m1, mx1);
        float f0 = exp2f(m0 - nm0);
        float f1 = exp2f(m1 - nm1);
        m0 = nm0; m1 = nm1;

        // p = exp2(s - m), packed directly into PV A-operand fragments
        uint32_t a[4][4];
        float sum0 = 0.f, sum1 = 0.f;
#pragma unroll
        for (int nt = 0; nt < 8; nt++) {
            float p0 = exp2f(s[nt][0] - nm0);
            float p1 = exp2f(s[nt][1] - nm0);
            float p2 = exp2f(s[nt][2] - nm1);
            float p3 = exp2f(s[nt][3] - nm1);
            sum0 += p0 + p1; sum1 += p2 + p3;
            int c = nt >> 1;
            if ((nt & 1) == 0) {
                a[c][0] = pack_f16(p0, p1);
                a[c][1] = pack_f16(p2, p3);
            } else {
                a[c][2] = pack_f16(p0, p1);
                a[c][3] = pack_f16(p2, p3);
            }
        }
        sum0 += __shfl_xor_sync(0xffffffffu, sum0, 1);
        sum0 += __shfl_xor_sync(0xffffffffu, sum0, 2);
        sum1 += __shfl_xor_sync(0xffffffffu, sum1, 1);
        sum1 += __shfl_xor_sync(0xffffffffu, sum1, 2);
        l0 = l0 * f0 + sum0;
        l1 = l1 * f1 + sum1;

        if (__any_sync(0xffffffffu, need)) {
#pragma unroll
            for (int nt = 0; nt < 8; nt++) {
                o[nt][0] *= f0; o[nt][1] *= f0;
                o[nt][2] *= f1; o[nt][3] *= f1;
            }
        }

        // ---- O += P @ V (P register-resident, V via LDSM) ----
#pragma unroll
        for (int c = 0; c < 4; c++) {
#pragma unroll
            for (int ntp = 0; ntp < 4; ntp++) {
                uint32_t b0, b1, b2, b3;
                ldsm_x4(b0, b1, b2, b3, va + ntp * (16 * US * 4) + c * 32);
                mma16(o[2 * ntp],     a[c][0], a[c][1], a[c][2], a[c][3], b0, b1);
                mma16(o[2 * ntp + 1], a[c][0], a[c][1], a[c][2], a[c][3], b2, b3);
            }
        }
        // no bottom barrier: stage reuse protected by next iteration's top
        // barrier (stage (kb+3)%3 == kb%3 only refilled at iter kb+1, after
        // every warp has passed the barrier following tile kb).
    }

    // ---- normalize + write fp16 ----
    float inv0 = 1.f / fmaxf(l0, 1e-20f);
    float inv1 = 1.f / fmaxf(l1, 1e-20f);
    uint32_t* Og = (uint32_t*)Oh;
#pragma unroll
    for (int nt = 0; nt < 8; nt++) {
        int cp = h * 32 + nt * 4 + tig;   // u32 (half-pair) column index
        Og[(size_t)(qb * 128 + r0) * (DMODEL / 2) + cp] =
            pack_f16(o[nt][0] * inv0, o[nt][1] * inv0);
        Og[(size_t)(qb * 128 + r0 + 8) * (DMODEL / 2) + cp] =
            pack_f16(o[nt][2] * inv1, o[nt][3] * inv1);
    }
#undef ISSUE_TILE
}

// ---------------------------------------------------------------------------
extern "C" void kernel_launch(void* const* d_in, const int* in_sizes, int n_in,
                              void* d_out, int out_size)
{
    (void)in_sizes; (void)n_in; (void)out_size;
    const float* query = (const float*)d_in[0];
    const float* key   = (const float*)d_in[1];
    const float* value = (const float*)d_in[2];
    const int*   amask = (const int*)  d_in[3];
    const float* Wq = (const float*)d_in[4];
    const float* bq = (const float*)d_in[5];
    const float* Wk = (const float*)d_in[6];
    const float* bk = (const float*)d_in[7];
    const float* Wv = (const float*)d_in[8];
    const float* bv = (const float*)d_in[9];
    const float* Wo = (const float*)d_in[10];
    const float* bo = (const float*)d_in[11];
    float* out = (float*)d_out;

    __half *Xq, *Xk, *Xv, *WqT, *WkT, *WvT, *WoT, *Qhp, *Khp, *VTp, *Ahp;
    float *msp;
    cudaGetSymbolAddress((void**)&Xq,  g_Xq);
    cudaGetSymbolAddress((void**)&Xk,  g_Xk);
    cudaGetSymbolAddress((void**)&Xv,  g_Xv);
    cudaGetSymbolAddress((void**)&WqT, g_WqT);
    cudaGetSymbolAddress((void**)&WkT, g_WkT);
    cudaGetSymbolAddress((void**)&WvT, g_WvT);
    cudaGetSymbolAddress((void**)&WoT, g_WoT);
    cudaGetSymbolAddress((void**)&Qhp, g_Qh);
    cudaGetSymbolAddress((void**)&Khp, g_Kh);
    cudaGetSymbolAddress((void**)&VTp, g_VT);
    cudaGetSymbolAddress((void**)&Ahp, g_Ah);
    cudaGetSymbolAddress((void**)&msp, g_ms);

    // Prepasses: activations->fp16, mask->float, weights->fp16 transposed
    cvt_act<<<dim3(S_LEN * DMODEL / 1024, 3), 256>>>(query, key, value, Xq, Xk, Xv);
    cvt_mask<<<S_LEN / 256, 256>>>(amask, msp);
    wtrans<<<dim3(DMODEL / 32, DMODEL / 32, 4), 256>>>(
        Wq, Wk, Wv, Wo, WqT, WkT, WvT, WoT);

    // Fused Q/K/V projections (pure fp16 cp.async GEMM; V pre-transposed)
    cudaFuncSetAttribute(gemm_qkv,
                         cudaFuncAttributeMaxDynamicSharedMemorySize, SMEM_GEMM);
    gemm_qkv<<<dim3(DMODEL / 128, S_LEN / 128, 3), 256, SMEM_GEMM>>>(
        Xq, Xk, Xv, WqT, bq, WkT, bk, WvT, bv, Qhp, Khp, VTp);

    cudaFuncSetAttribute(attn_f16,
                         cudaFuncAttributeMaxDynamicSharedMemorySize, SMEM_ATT);
    attn_f16<<<dim3(NHEADS, S_LEN / 128), 256, SMEM_ATT>>>(Qhp, Khp, VTp, msp, Ahp);

    cudaFuncSetAttribute(gemm_out,
                         cudaFuncAttributeMaxDynamicSharedMemorySize, SMEM_GEMM);
    gemm_out<<<dim3(DMODEL / 128, S_LEN / 128), 256, SMEM_GEMM>>>(Ahp, WoT, bo, out);
}